// round 8
// baseline (speedup 1.0000x reference)
#include <cuda_runtime.h>

// Problem constants (fixed shapes from reference)
#define BB 16
#define HH 512
#define WW 512
#define H2 1024
#define W2 1024
#define WV (W2 / 4)    // float4 vectors per output row = 256
#define HT (HH / 2)    // 4-row tiles per batch = 256

// Fused: bilinear 2x upsample of mask (2ch) -> x_mask,y_mask;
// fused_c = xm*xl_c + ym*yl_c; out_o = relu(sum_i w[o,i]*fused_i + b_o).
// R8: 4 output rows x 4 cols per thread, PHASED: all 24 stream loads
// front-batched, then all compute, then all 20 stores back-to-back.
__global__ void __launch_bounds__(256) fused_upsample_blend_conv_kernel(
    const float* __restrict__ mask,   // (B,2,H,W)
    const float* __restrict__ xl,     // (B,3,H2,W2)
    const float* __restrict__ yl,     // (B,3,H2,W2)
    const float* __restrict__ cw,     // (3,3) row-major 'oi'
    const float* __restrict__ cb,     // (3,)
    float* __restrict__ out)          // (B,3,H2,W2) ++ (B,1,H2,W2) ++ (B,1,H2,W2)
{
    int idx = blockIdx.x * blockDim.x + threadIdx.x;
    int ox4 = idx & (WV - 1);        // vector index along width
    int t   = idx >> 8;              // WV = 256
    int j   = t & (HT - 1);          // 4-row tile index
    int b   = t >> 8;                // HT = 256
    if (b >= BB) return;

    const int kb = 2 * j;            // input base row (even): rows kb-1..kb+2
    int rA = kb - 1; if (rA < 0) rA = 0;
    const int rB = kb;
    const int rC = kb + 1;
    int rD = kb + 2; if (rD > HH - 1) rD = HH - 1;

    int m   = ox4 * 2;               // 0..510, even
    int cm1 = m - 1; if (cm1 < 0) cm1 = 0;
    int cp1 = m + 1;
    int cp2 = m + 2; if (cp2 > WW - 1) cp2 = WW - 1;

    const size_t plane = (size_t)H2 * W2;
    const int oy0 = 4 * j;
    const size_t base0 = (size_t)b * 3 * plane + (size_t)oy0 * W2 + (size_t)ox4 * 4;

    // ================= PHASE 1: all global loads, front-batched =============
    // 24 stream float4 loads (xl/yl x 3ch x 4 rows)
    float4 xc[3][4], yc[3][4];
    #pragma unroll
    for (int c = 0; c < 3; c++) {
        #pragma unroll
        for (int r = 0; r < 4; r++) {
            xc[c][r] = *(const float4*)(xl + base0 + (size_t)c * plane + (size_t)r * W2);
        }
    }
    #pragma unroll
    for (int c = 0; c < 3; c++) {
        #pragma unroll
        for (int r = 0; r < 4; r++) {
            yc[c][r] = *(const float4*)(yl + base0 + (size_t)c * plane + (size_t)r * W2);
        }
    }

    // 32 scalar mask loads (4 rows x 4 cols x 2 channels)
    const size_t mplane = (size_t)HH * WW;
    const float* mx = mask + ((size_t)b * 2 + 0) * mplane;
    const float* my = mask + ((size_t)b * 2 + 1) * mplane;
    const float* pxA = mx + (size_t)rA * WW;  const float* pxB = mx + (size_t)rB * WW;
    const float* pxC = mx + (size_t)rC * WW;  const float* pxD = mx + (size_t)rD * WW;
    const float* pyA = my + (size_t)rA * WW;  const float* pyB = my + (size_t)rB * WW;
    const float* pyC = my + (size_t)rC * WW;  const float* pyD = my + (size_t)rD * WW;

    float xA0=__ldg(pxA+cm1), xA1=__ldg(pxA+m), xA2=__ldg(pxA+cp1), xA3=__ldg(pxA+cp2);
    float xB0=__ldg(pxB+cm1), xB1=__ldg(pxB+m), xB2=__ldg(pxB+cp1), xB3=__ldg(pxB+cp2);
    float xC0=__ldg(pxC+cm1), xC1=__ldg(pxC+m), xC2=__ldg(pxC+cp1), xC3=__ldg(pxC+cp2);
    float xD0=__ldg(pxD+cm1), xD1=__ldg(pxD+m), xD2=__ldg(pxD+cp1), xD3=__ldg(pxD+cp2);
    float yA0=__ldg(pyA+cm1), yA1=__ldg(pyA+m), yA2=__ldg(pyA+cp1), yA3=__ldg(pyA+cp2);
    float yB0=__ldg(pyB+cm1), yB1=__ldg(pyB+m), yB2=__ldg(pyB+cp1), yB3=__ldg(pyB+cp2);
    float yC0=__ldg(pyC+cm1), yC1=__ldg(pyC+m), yC2=__ldg(pyC+cp1), yC3=__ldg(pyC+cp2);
    float yD0=__ldg(pyD+cm1), yD1=__ldg(pyD+m), yD2=__ldg(pyD+cp1), yD3=__ldg(pyD+cp2);

    float w00 = __ldg(cw + 0), w01 = __ldg(cw + 1), w02 = __ldg(cw + 2);
    float w10 = __ldg(cw + 3), w11 = __ldg(cw + 4), w12 = __ldg(cw + 5);
    float w20 = __ldg(cw + 6), w21 = __ldg(cw + 7), w22 = __ldg(cw + 8);
    float b0 = __ldg(cb + 0), b1 = __ldg(cb + 1), b2 = __ldg(cb + 2);

    // ================= PHASE 2: compute =====================================
    // vertical interpolation per input column: 4 output rows
    float vx[4][4], vy[4][4];
    vx[0][0]=0.25f*xA0+0.75f*xB0; vx[0][1]=0.25f*xA1+0.75f*xB1; vx[0][2]=0.25f*xA2+0.75f*xB2; vx[0][3]=0.25f*xA3+0.75f*xB3;
    vx[1][0]=0.75f*xB0+0.25f*xC0; vx[1][1]=0.75f*xB1+0.25f*xC1; vx[1][2]=0.75f*xB2+0.25f*xC2; vx[1][3]=0.75f*xB3+0.25f*xC3;
    vx[2][0]=0.25f*xB0+0.75f*xC0; vx[2][1]=0.25f*xB1+0.75f*xC1; vx[2][2]=0.25f*xB2+0.75f*xC2; vx[2][3]=0.25f*xB3+0.75f*xC3;
    vx[3][0]=0.75f*xC0+0.25f*xD0; vx[3][1]=0.75f*xC1+0.25f*xD1; vx[3][2]=0.75f*xC2+0.25f*xD2; vx[3][3]=0.75f*xC3+0.25f*xD3;
    vy[0][0]=0.25f*yA0+0.75f*yB0; vy[0][1]=0.25f*yA1+0.75f*yB1; vy[0][2]=0.25f*yA2+0.75f*yB2; vy[0][3]=0.25f*yA3+0.75f*yB3;
    vy[1][0]=0.75f*yB0+0.25f*yC0; vy[1][1]=0.75f*yB1+0.25f*yC1; vy[1][2]=0.75f*yB2+0.25f*yC2; vy[1][3]=0.75f*yB3+0.25f*yC3;
    vy[2][0]=0.25f*yB0+0.75f*yC0; vy[2][1]=0.25f*yB1+0.75f*yC1; vy[2][2]=0.25f*yB2+0.75f*yC2; vy[2][3]=0.25f*yB3+0.75f*yC3;
    vy[3][0]=0.75f*yC0+0.25f*yD0; vy[3][1]=0.75f*yC1+0.25f*yD1; vy[3][2]=0.75f*yC2+0.25f*yD2; vy[3][3]=0.75f*yC3+0.25f*yD3;

    // horizontal combine -> per-row 4-wide masks
    float xm[4][4], ym[4][4];
    #pragma unroll
    for (int r = 0; r < 4; r++) {
        xm[r][0] = 0.25f*vx[r][0] + 0.75f*vx[r][1];
        xm[r][1] = 0.75f*vx[r][1] + 0.25f*vx[r][2];
        xm[r][2] = 0.25f*vx[r][1] + 0.75f*vx[r][2];
        xm[r][3] = 0.75f*vx[r][2] + 0.25f*vx[r][3];
        ym[r][0] = 0.25f*vy[r][0] + 0.75f*vy[r][1];
        ym[r][1] = 0.75f*vy[r][1] + 0.25f*vy[r][2];
        ym[r][2] = 0.25f*vy[r][1] + 0.75f*vy[r][2];
        ym[r][3] = 0.75f*vy[r][2] + 0.25f*vy[r][3];
    }

    // blend + channel mix + relu, overwriting xc[][] with outputs (reg reuse)
    #pragma unroll
    for (int r = 0; r < 4; r++) {
        float f0[4] = { xm[r][0]*xc[0][r].x + ym[r][0]*yc[0][r].x,
                        xm[r][1]*xc[0][r].y + ym[r][1]*yc[0][r].y,
                        xm[r][2]*xc[0][r].z + ym[r][2]*yc[0][r].z,
                        xm[r][3]*xc[0][r].w + ym[r][3]*yc[0][r].w };
        float f1[4] = { xm[r][0]*xc[1][r].x + ym[r][0]*yc[1][r].x,
                        xm[r][1]*xc[1][r].y + ym[r][1]*yc[1][r].y,
                        xm[r][2]*xc[1][r].z + ym[r][2]*yc[1][r].z,
                        xm[r][3]*xc[1][r].w + ym[r][3]*yc[1][r].w };
        float f2[4] = { xm[r][0]*xc[2][r].x + ym[r][0]*yc[2][r].x,
                        xm[r][1]*xc[2][r].y + ym[r][1]*yc[2][r].y,
                        xm[r][2]*xc[2][r].z + ym[r][2]*yc[2][r].z,
                        xm[r][3]*xc[2][r].w + ym[r][3]*yc[2][r].w };

        float o0[4], o1[4], o2[4];
        #pragma unroll
        for (int q = 0; q < 4; q++) {
            float v0 = w00 * f0[q] + w01 * f1[q] + w02 * f2[q] + b0;
            float v1 = w10 * f0[q] + w11 * f1[q] + w12 * f2[q] + b1;
            float v2 = w20 * f0[q] + w21 * f1[q] + w22 * f2[q] + b2;
            o0[q] = v0 > 0.0f ? v0 : 0.0f;
            o1[q] = v1 > 0.0f ? v1 : 0.0f;
            o2[q] = v2 > 0.0f ? v2 : 0.0f;
        }
        xc[0][r] = make_float4(o0[0], o0[1], o0[2], o0[3]);
        xc[1][r] = make_float4(o1[0], o1[1], o1[2], o1[3]);
        xc[2][r] = make_float4(o2[0], o2[1], o2[2], o2[3]);
    }

    // ================= PHASE 3: all stores, back-to-back ====================
    float* out_main = out;                                   // (B,3,H2,W2)
    float* out_xm   = out + (size_t)BB * 3 * plane;          // (B,1,H2,W2)
    float* out_ym   = out_xm + (size_t)BB * plane;           // (B,1,H2,W2)
    const size_t mbase0 = (size_t)b * plane + (size_t)oy0 * W2 + (size_t)ox4 * 4;

    #pragma unroll
    for (int c = 0; c < 3; c++) {
        #pragma unroll
        for (int r = 0; r < 4; r++) {
            *(float4*)(out_main + base0 + (size_t)c * plane + (size_t)r * W2) = xc[c][r];
        }
    }
    #pragma unroll
    for (int r = 0; r < 4; r++) {
        *(float4*)(out_xm + mbase0 + (size_t)r * W2) = make_float4(xm[r][0], xm[r][1], xm[r][2], xm[r][3]);
    }
    #pragma unroll
    for (int r = 0; r < 4; r++) {
        *(float4*)(out_ym + mbase0 + (size_t)r * W2) = make_float4(ym[r][0], ym[r][1], ym[r][2], ym[r][3]);
    }
}

extern "C" void kernel_launch(void* const* d_in, const int* in_sizes, int n_in,
                              void* d_out, int out_size) {
    const float* mask = (const float*)d_in[0];
    const float* xl   = (const float*)d_in[1];
    const float* yl   = (const float*)d_in[2];
    const float* cw   = (const float*)d_in[3];
    const float* cb   = (const float*)d_in[4];
    float* out = (float*)d_out;

    const int total = BB * HT * WV;          // 1,048,576 threads (4 rows each)
    const int threads = 256;
    const int blocks = (total + threads - 1) / threads;
    fused_upsample_blend_conv_kernel<<<blocks, threads>>>(mask, xl, yl, cw, cb, out);
}

// round 9
// speedup vs baseline: 1.2099x; 1.2099x over previous
#include <cuda_runtime.h>

// Problem constants (fixed shapes from reference)
#define BB 16
#define HH 512
#define WW 512
#define H2 1024
#define W2 1024
#define WV (W2 / 4)   // float4 vectors per output row

// Fused: bilinear 2x upsample of mask (2ch) -> x_mask,y_mask;
// fused_c = xm*xl_c + ym*yl_c; out_o = relu(sum_i w[o,i]*fused_i + b_o).
// R9: R3's 2-row x 4-col tile (12 front-batched LDG.128), with
// __launch_bounds__(256, 4) capping regs at 64 -> 4 CTAs/SM resident.
__global__ void __launch_bounds__(256, 4) fused_upsample_blend_conv_kernel(
    const float* __restrict__ mask,   // (B,2,H,W)
    const float* __restrict__ xl,     // (B,3,H2,W2)
    const float* __restrict__ yl,     // (B,3,H2,W2)
    const float* __restrict__ cw,     // (3,3) row-major 'oi'
    const float* __restrict__ cb,     // (3,)
    float* __restrict__ out)          // (B,3,H2,W2) ++ (B,1,H2,W2) ++ (B,1,H2,W2)
{
    int idx = blockIdx.x * blockDim.x + threadIdx.x;
    int ox4 = idx & (WV - 1);        // vector index along width
    int t   = idx >> 8;              // WV = 256
    int k   = t & (HH - 1);          // input row / output row-pair index
    int b   = t >> 9;                // HH = 512
    if (b >= BB) return;

    // Output rows: oy0 = 2k (even, taps rows k-1,k w 0.25/0.75)
    //              oy1 = 2k+1 (odd, taps rows k,k+1 w 0.75/0.25)
    int km1 = k - 1; if (km1 < 0) km1 = 0;
    int kp1 = k + 1; if (kp1 > HH - 1) kp1 = HH - 1;

    // ---- horizontal: 4 outputs share input cols {m-1, m, m+1, m+2} ----
    int m   = ox4 * 2;                       // 0..510, even
    int cm1 = m - 1; if (cm1 < 0) cm1 = 0;
    int cp1 = m + 1;                         // <= 511 always
    int cp2 = m + 2; if (cp2 > WW - 1) cp2 = WW - 1;

    const size_t mplane = (size_t)HH * WW;
    const float* mx = mask + ((size_t)b * 2 + 0) * mplane;
    const float* my = mask + ((size_t)b * 2 + 1) * mplane;
    const float* mx_m = mx + (size_t)km1 * WW;
    const float* mx_0 = mx + (size_t)k   * WW;
    const float* mx_p = mx + (size_t)kp1 * WW;
    const float* my_m = my + (size_t)km1 * WW;
    const float* my_0 = my + (size_t)k   * WW;
    const float* my_p = my + (size_t)kp1 * WW;

    // raw mask samples: 3 rows x 4 cols x 2 channels
    float xA0 = __ldg(mx_m + cm1), xA1 = __ldg(mx_m + m), xA2 = __ldg(mx_m + cp1), xA3 = __ldg(mx_m + cp2);
    float xB0 = __ldg(mx_0 + cm1), xB1 = __ldg(mx_0 + m), xB2 = __ldg(mx_0 + cp1), xB3 = __ldg(mx_0 + cp2);
    float xC0 = __ldg(mx_p + cm1), xC1 = __ldg(mx_p + m), xC2 = __ldg(mx_p + cp1), xC3 = __ldg(mx_p + cp2);
    float yA0 = __ldg(my_m + cm1), yA1 = __ldg(my_m + m), yA2 = __ldg(my_m + cp1), yA3 = __ldg(my_m + cp2);
    float yB0 = __ldg(my_0 + cm1), yB1 = __ldg(my_0 + m), yB2 = __ldg(my_0 + cp1), yB3 = __ldg(my_0 + cp2);
    float yC0 = __ldg(my_p + cm1), yC1 = __ldg(my_p + m), yC2 = __ldg(my_p + cp1), yC3 = __ldg(my_p + cp2);

    // vertical interpolation per input column, for even (e) and odd (o) rows
    float vxe0 = 0.25f*xA0 + 0.75f*xB0, vxe1 = 0.25f*xA1 + 0.75f*xB1;
    float vxe2 = 0.25f*xA2 + 0.75f*xB2, vxe3 = 0.25f*xA3 + 0.75f*xB3;
    float vxo0 = 0.75f*xB0 + 0.25f*xC0, vxo1 = 0.75f*xB1 + 0.25f*xC1;
    float vxo2 = 0.75f*xB2 + 0.25f*xC2, vxo3 = 0.75f*xB3 + 0.25f*xC3;
    float vye0 = 0.25f*yA0 + 0.75f*yB0, vye1 = 0.25f*yA1 + 0.75f*yB1;
    float vye2 = 0.25f*yA2 + 0.75f*yB2, vye3 = 0.25f*yA3 + 0.75f*yB3;
    float vyo0 = 0.75f*yB0 + 0.25f*yC0, vyo1 = 0.75f*yB1 + 0.25f*yC1;
    float vyo2 = 0.75f*yB2 + 0.25f*yC2, vyo3 = 0.75f*yB3 + 0.25f*yC3;

    // horizontal combine -> per-row 4-wide masks
    float xme[4], xmo[4], yme[4], ymo[4];
    xme[0] = 0.25f*vxe0 + 0.75f*vxe1;  xme[1] = 0.75f*vxe1 + 0.25f*vxe2;
    xme[2] = 0.25f*vxe1 + 0.75f*vxe2;  xme[3] = 0.75f*vxe2 + 0.25f*vxe3;
    xmo[0] = 0.25f*vxo0 + 0.75f*vxo1;  xmo[1] = 0.75f*vxo1 + 0.25f*vxo2;
    xmo[2] = 0.25f*vxo1 + 0.75f*vxo2;  xmo[3] = 0.75f*vxo2 + 0.25f*vxo3;
    yme[0] = 0.25f*vye0 + 0.75f*vye1;  yme[1] = 0.75f*vye1 + 0.25f*vye2;
    yme[2] = 0.25f*vye1 + 0.75f*vye2;  yme[3] = 0.75f*vye2 + 0.25f*vye3;
    ymo[0] = 0.25f*vyo0 + 0.75f*vyo1;  ymo[1] = 0.75f*vyo1 + 0.25f*vyo2;
    ymo[2] = 0.25f*vyo1 + 0.75f*vyo2;  ymo[3] = 0.75f*vyo2 + 0.25f*vyo3;

    // ---- load xl/yl: 2 rows x 3 channels x 2 tensors = 12 float4 ----
    const size_t plane = (size_t)H2 * W2;
    const int oy0 = 2 * k;
    const size_t base0 = (size_t)b * 3 * plane + (size_t)oy0 * W2 + (size_t)ox4 * 4;
    const size_t base1 = base0 + W2;   // odd row

    float4 xe0 = *(const float4*)(xl + base0);
    float4 xe1 = *(const float4*)(xl + base0 + plane);
    float4 xe2 = *(const float4*)(xl + base0 + 2 * plane);
    float4 xo0 = *(const float4*)(xl + base1);
    float4 xo1 = *(const float4*)(xl + base1 + plane);
    float4 xo2 = *(const float4*)(xl + base1 + 2 * plane);
    float4 ye0 = *(const float4*)(yl + base0);
    float4 ye1 = *(const float4*)(yl + base0 + plane);
    float4 ye2 = *(const float4*)(yl + base0 + 2 * plane);
    float4 yo0 = *(const float4*)(yl + base1);
    float4 yo1 = *(const float4*)(yl + base1 + plane);
    float4 yo2 = *(const float4*)(yl + base1 + 2 * plane);

    // conv weights / bias
    float w00 = __ldg(cw + 0), w01 = __ldg(cw + 1), w02 = __ldg(cw + 2);
    float w10 = __ldg(cw + 3), w11 = __ldg(cw + 4), w12 = __ldg(cw + 5);
    float w20 = __ldg(cw + 6), w21 = __ldg(cw + 7), w22 = __ldg(cw + 8);
    float b0 = __ldg(cb + 0), b1 = __ldg(cb + 1), b2 = __ldg(cb + 2);

    float* out_main = out;                                   // (B,3,H2,W2)
    float* out_xm   = out + (size_t)BB * 3 * plane;          // (B,1,H2,W2)
    float* out_ym   = out_xm + (size_t)BB * plane;           // (B,1,H2,W2)

    // ---- per-row: blend, channel-mix, relu, store ----
    #pragma unroll
    for (int r = 0; r < 2; r++) {
        const float* xm = r ? xmo : xme;
        const float* ym = r ? ymo : yme;
        float4 c0 = r ? xo0 : xe0, c1 = r ? xo1 : xe1, c2 = r ? xo2 : xe2;
        float4 d0 = r ? yo0 : ye0, d1 = r ? yo1 : ye1, d2 = r ? yo2 : ye2;
        size_t base = r ? base1 : base0;

        float f0[4] = { xm[0]*c0.x + ym[0]*d0.x, xm[1]*c0.y + ym[1]*d0.y,
                        xm[2]*c0.z + ym[2]*d0.z, xm[3]*c0.w + ym[3]*d0.w };
        float f1[4] = { xm[0]*c1.x + ym[0]*d1.x, xm[1]*c1.y + ym[1]*d1.y,
                        xm[2]*c1.z + ym[2]*d1.z, xm[3]*c1.w + ym[3]*d1.w };
        float f2[4] = { xm[0]*c2.x + ym[0]*d2.x, xm[1]*c2.y + ym[1]*d2.y,
                        xm[2]*c2.z + ym[2]*d2.z, xm[3]*c2.w + ym[3]*d2.w };

        float4 o0, o1, o2;
        {
            float rr[4];
            #pragma unroll
            for (int q = 0; q < 4; q++) {
                float v = w00 * f0[q] + w01 * f1[q] + w02 * f2[q] + b0;
                rr[q] = v > 0.0f ? v : 0.0f;
            }
            o0 = make_float4(rr[0], rr[1], rr[2], rr[3]);
            #pragma unroll
            for (int q = 0; q < 4; q++) {
                float v = w10 * f0[q] + w11 * f1[q] + w12 * f2[q] + b1;
                rr[q] = v > 0.0f ? v : 0.0f;
            }
            o1 = make_float4(rr[0], rr[1], rr[2], rr[3]);
            #pragma unroll
            for (int q = 0; q < 4; q++) {
                float v = w20 * f0[q] + w21 * f1[q] + w22 * f2[q] + b2;
                rr[q] = v > 0.0f ? v : 0.0f;
            }
            o2 = make_float4(rr[0], rr[1], rr[2], rr[3]);
        }

        *(float4*)(out_main + base)             = o0;
        *(float4*)(out_main + base + plane)     = o1;
        *(float4*)(out_main + base + 2 * plane) = o2;

        size_t mbase = (size_t)b * plane + (size_t)(oy0 + r) * W2 + (size_t)ox4 * 4;
        *(float4*)(out_xm + mbase) = make_float4(xm[0], xm[1], xm[2], xm[3]);
        *(float4*)(out_ym + mbase) = make_float4(ym[0], ym[1], ym[2], ym[3]);
    }
}

extern "C" void kernel_launch(void* const* d_in, const int* in_sizes, int n_in,
                              void* d_out, int out_size) {
    const float* mask = (const float*)d_in[0];
    const float* xl   = (const float*)d_in[1];
    const float* yl   = (const float*)d_in[2];
    const float* cw   = (const float*)d_in[3];
    const float* cb   = (const float*)d_in[4];
    float* out = (float*)d_out;

    const int total = BB * HH * WV;          // 2,097,152 threads (2 rows each)
    const int threads = 256;
    const int blocks = (total + threads - 1) / threads;
    fused_upsample_blend_conv_kernel<<<blocks, threads>>>(mask, xl, yl, cw, cb, out);
}

// round 10
// speedup vs baseline: 1.2116x; 1.0014x over previous
#include <cuda_runtime.h>

// Problem constants (fixed shapes from reference)
#define BB 16
#define HH 512
#define WW 512
#define H2 1024
#define W2 1024
#define WV (W2 / 4)   // float4 vectors per output row

// Fused: bilinear 2x upsample of mask (2ch) -> x_mask,y_mask;
// fused_c = xm*xl_c + ym*yl_c; out_o = relu(sum_i w[o,i]*fused_i + b_o).
// R10: R9 (2-row x 4-col tile, launch_bounds(256,4) -> 64 regs, 4 CTA/SM)
// with the 12 DRAM-bound stream LDG.128 issued FIRST, mask L2-hit loads after.
__global__ void __launch_bounds__(256, 4) fused_upsample_blend_conv_kernel(
    const float* __restrict__ mask,   // (B,2,H,W)
    const float* __restrict__ xl,     // (B,3,H2,W2)
    const float* __restrict__ yl,     // (B,3,H2,W2)
    const float* __restrict__ cw,     // (3,3) row-major 'oi'
    const float* __restrict__ cb,     // (3,)
    float* __restrict__ out)          // (B,3,H2,W2) ++ (B,1,H2,W2) ++ (B,1,H2,W2)
{
    int idx = blockIdx.x * blockDim.x + threadIdx.x;
    int ox4 = idx & (WV - 1);        // vector index along width
    int t   = idx >> 8;              // WV = 256
    int k   = t & (HH - 1);          // input row / output row-pair index
    int b   = t >> 9;                // HH = 512
    if (b >= BB) return;

    // ---- stream loads FIRST: 2 rows x 3 channels x 2 tensors = 12 float4 ----
    const size_t plane = (size_t)H2 * W2;
    const int oy0 = 2 * k;
    const size_t base0 = (size_t)b * 3 * plane + (size_t)oy0 * W2 + (size_t)ox4 * 4;
    const size_t base1 = base0 + W2;   // odd row

    float4 xe0 = *(const float4*)(xl + base0);
    float4 xe1 = *(const float4*)(xl + base0 + plane);
    float4 xe2 = *(const float4*)(xl + base0 + 2 * plane);
    float4 xo0 = *(const float4*)(xl + base1);
    float4 xo1 = *(const float4*)(xl + base1 + plane);
    float4 xo2 = *(const float4*)(xl + base1 + 2 * plane);
    float4 ye0 = *(const float4*)(yl + base0);
    float4 ye1 = *(const float4*)(yl + base0 + plane);
    float4 ye2 = *(const float4*)(yl + base0 + 2 * plane);
    float4 yo0 = *(const float4*)(yl + base1);
    float4 yo1 = *(const float4*)(yl + base1 + plane);
    float4 yo2 = *(const float4*)(yl + base1 + 2 * plane);

    // ---- mask loads second (mostly L2 hits) ----
    // Output rows: oy0 = 2k (even, taps rows k-1,k w 0.25/0.75)
    //              oy1 = 2k+1 (odd, taps rows k,k+1 w 0.75/0.25)
    int km1 = k - 1; if (km1 < 0) km1 = 0;
    int kp1 = k + 1; if (kp1 > HH - 1) kp1 = HH - 1;

    int m   = ox4 * 2;                       // 0..510, even
    int cm1 = m - 1; if (cm1 < 0) cm1 = 0;
    int cp1 = m + 1;                         // <= 511 always
    int cp2 = m + 2; if (cp2 > WW - 1) cp2 = WW - 1;

    const size_t mplane = (size_t)HH * WW;
    const float* mx = mask + ((size_t)b * 2 + 0) * mplane;
    const float* my = mask + ((size_t)b * 2 + 1) * mplane;
    const float* mx_m = mx + (size_t)km1 * WW;
    const float* mx_0 = mx + (size_t)k   * WW;
    const float* mx_p = mx + (size_t)kp1 * WW;
    const float* my_m = my + (size_t)km1 * WW;
    const float* my_0 = my + (size_t)k   * WW;
    const float* my_p = my + (size_t)kp1 * WW;

    float xA0 = __ldg(mx_m + cm1), xA1 = __ldg(mx_m + m), xA2 = __ldg(mx_m + cp1), xA3 = __ldg(mx_m + cp2);
    float xB0 = __ldg(mx_0 + cm1), xB1 = __ldg(mx_0 + m), xB2 = __ldg(mx_0 + cp1), xB3 = __ldg(mx_0 + cp2);
    float xC0 = __ldg(mx_p + cm1), xC1 = __ldg(mx_p + m), xC2 = __ldg(mx_p + cp1), xC3 = __ldg(mx_p + cp2);
    float yA0 = __ldg(my_m + cm1), yA1 = __ldg(my_m + m), yA2 = __ldg(my_m + cp1), yA3 = __ldg(my_m + cp2);
    float yB0 = __ldg(my_0 + cm1), yB1 = __ldg(my_0 + m), yB2 = __ldg(my_0 + cp1), yB3 = __ldg(my_0 + cp2);
    float yC0 = __ldg(my_p + cm1), yC1 = __ldg(my_p + m), yC2 = __ldg(my_p + cp1), yC3 = __ldg(my_p + cp2);

    // vertical interpolation per input column, for even (e) and odd (o) rows
    float vxe0 = 0.25f*xA0 + 0.75f*xB0, vxe1 = 0.25f*xA1 + 0.75f*xB1;
    float vxe2 = 0.25f*xA2 + 0.75f*xB2, vxe3 = 0.25f*xA3 + 0.75f*xB3;
    float vxo0 = 0.75f*xB0 + 0.25f*xC0, vxo1 = 0.75f*xB1 + 0.25f*xC1;
    float vxo2 = 0.75f*xB2 + 0.25f*xC2, vxo3 = 0.75f*xB3 + 0.25f*xC3;
    float vye0 = 0.25f*yA0 + 0.75f*yB0, vye1 = 0.25f*yA1 + 0.75f*yB1;
    float vye2 = 0.25f*yA2 + 0.75f*yB2, vye3 = 0.25f*yA3 + 0.75f*yB3;
    float vyo0 = 0.75f*yB0 + 0.25f*yC0, vyo1 = 0.75f*yB1 + 0.25f*yC1;
    float vyo2 = 0.75f*yB2 + 0.25f*yC2, vyo3 = 0.75f*yB3 + 0.25f*yC3;

    // horizontal combine -> per-row 4-wide masks
    float xme[4], xmo[4], yme[4], ymo[4];
    xme[0] = 0.25f*vxe0 + 0.75f*vxe1;  xme[1] = 0.75f*vxe1 + 0.25f*vxe2;
    xme[2] = 0.25f*vxe1 + 0.75f*vxe2;  xme[3] = 0.75f*vxe2 + 0.25f*vxe3;
    xmo[0] = 0.25f*vxo0 + 0.75f*vxo1;  xmo[1] = 0.75f*vxo1 + 0.25f*vxo2;
    xmo[2] = 0.25f*vxo1 + 0.75f*vxo2;  xmo[3] = 0.75f*vxo2 + 0.25f*vxo3;
    yme[0] = 0.25f*vye0 + 0.75f*vye1;  yme[1] = 0.75f*vye1 + 0.25f*vye2;
    yme[2] = 0.25f*vye1 + 0.75f*vye2;  yme[3] = 0.75f*vye2 + 0.25f*vye3;
    ymo[0] = 0.25f*vyo0 + 0.75f*vyo1;  ymo[1] = 0.75f*vyo1 + 0.25f*vyo2;
    ymo[2] = 0.25f*vyo1 + 0.75f*vyo2;  ymo[3] = 0.75f*vyo2 + 0.25f*vyo3;

    // conv weights / bias
    float w00 = __ldg(cw + 0), w01 = __ldg(cw + 1), w02 = __ldg(cw + 2);
    float w10 = __ldg(cw + 3), w11 = __ldg(cw + 4), w12 = __ldg(cw + 5);
    float w20 = __ldg(cw + 6), w21 = __ldg(cw + 7), w22 = __ldg(cw + 8);
    float b0 = __ldg(cb + 0), b1 = __ldg(cb + 1), b2 = __ldg(cb + 2);

    float* out_main = out;                                   // (B,3,H2,W2)
    float* out_xm   = out + (size_t)BB * 3 * plane;          // (B,1,H2,W2)
    float* out_ym   = out_xm + (size_t)BB * plane;           // (B,1,H2,W2)

    // ---- per-row: blend, channel-mix, relu, store ----
    #pragma unroll
    for (int r = 0; r < 2; r++) {
        const float* xm = r ? xmo : xme;
        const float* ym = r ? ymo : yme;
        float4 c0 = r ? xo0 : xe0, c1 = r ? xo1 : xe1, c2 = r ? xo2 : xe2;
        float4 d0 = r ? yo0 : ye0, d1 = r ? yo1 : ye1, d2 = r ? yo2 : ye2;
        size_t base = r ? base1 : base0;

        float f0[4] = { xm[0]*c0.x + ym[0]*d0.x, xm[1]*c0.y + ym[1]*d0.y,
                        xm[2]*c0.z + ym[2]*d0.z, xm[3]*c0.w + ym[3]*d0.w };
        float f1[4] = { xm[0]*c1.x + ym[0]*d1.x, xm[1]*c1.y + ym[1]*d1.y,
                        xm[2]*c1.z + ym[2]*d1.z, xm[3]*c1.w + ym[3]*d1.w };
        float f2[4] = { xm[0]*c2.x + ym[0]*d2.x, xm[1]*c2.y + ym[1]*d2.y,
                        xm[2]*c2.z + ym[2]*d2.z, xm[3]*c2.w + ym[3]*d2.w };

        float4 o0, o1, o2;
        {
            float rr[4];
            #pragma unroll
            for (int q = 0; q < 4; q++) {
                float v = w00 * f0[q] + w01 * f1[q] + w02 * f2[q] + b0;
                rr[q] = v > 0.0f ? v : 0.0f;
            }
            o0 = make_float4(rr[0], rr[1], rr[2], rr[3]);
            #pragma unroll
            for (int q = 0; q < 4; q++) {
                float v = w10 * f0[q] + w11 * f1[q] + w12 * f2[q] + b1;
                rr[q] = v > 0.0f ? v : 0.0f;
            }
            o1 = make_float4(rr[0], rr[1], rr[2], rr[3]);
            #pragma unroll
            for (int q = 0; q < 4; q++) {
                float v = w20 * f0[q] + w21 * f1[q] + w22 * f2[q] + b2;
                rr[q] = v > 0.0f ? v : 0.0f;
            }
            o2 = make_float4(rr[0], rr[1], rr[2], rr[3]);
        }

        *(float4*)(out_main + base)             = o0;
        *(float4*)(out_main + base + plane)     = o1;
        *(float4*)(out_main + base + 2 * plane) = o2;

        size_t mbase = (size_t)b * plane + (size_t)(oy0 + r) * W2 + (size_t)ox4 * 4;
        *(float4*)(out_xm + mbase) = make_float4(xm[0], xm[1], xm[2], xm[3]);
        *(float4*)(out_ym + mbase) = make_float4(ym[0], ym[1], ym[2], ym[3]);
    }
}

extern "C" void kernel_launch(void* const* d_in, const int* in_sizes, int n_in,
                              void* d_out, int out_size) {
    const float* mask = (const float*)d_in[0];
    const float* xl   = (const float*)d_in[1];
    const float* yl   = (const float*)d_in[2];
    const float* cw   = (const float*)d_in[3];
    const float* cb   = (const float*)d_in[4];
    float* out = (float*)d_out;

    const int total = BB * HH * WV;          // 2,097,152 threads (2 rows each)
    const int threads = 256;
    const int blocks = (total + threads - 1) / threads;
    fused_upsample_blend_conv_kernel<<<blocks, threads>>>(mask, xl, yl, cw, cb, out);
}